// round 2
// baseline (speedup 1.0000x reference)
#include <cuda_runtime.h>
#include <cstddef>

#define WB     1024
#define NTOK   128
#define NHEADS 8
#define HD     16

// ---------------- scratch (device globals; no runtime allocation) ----------
__device__ float g_qkv_self[(size_t)WB * NTOK * 384];   // [b][t][{q,k,v}*C]
__device__ float g_qkv_mut [(size_t)WB * NTOK * 384];
__device__ float g_concat  [(size_t)WB * NTOK * 256];   // [b][t][mut(128) | self(128)]
__device__ float g_bias    [NHEADS * NTOK * NTOK];      // [h][i][m]

// ---------------- rpe bias gather ------------------------------------------
__global__ void bias_prep(const int* __restrict__ rpe_index,
                          const float* __restrict__ rpe_table)
{
    int idx = blockIdx.x * 256 + threadIdx.x;        // 0 .. 16383  (= i*128+m)
    int t = rpe_index[idx];
#pragma unroll
    for (int h = 0; h < NHEADS; ++h)
        g_bias[h * 16384 + idx] = rpe_table[t * NHEADS + h];
}

// ---------------- generic 64x64-tile fp32 GEMM -----------------------------
// C[M,LDC slice] = A[M,KTOT] * W[N,KTOT]^T  (+ optional PE on A, bias on C)
// grid = (M/64, Ncols/64), block = 256 (16x16 threads, 4x4 microtile)
template<int KTOT, int LDC, bool PE, bool BIAS>
__global__ void __launch_bounds__(256) gemm64(
    const float* __restrict__ A, const float* __restrict__ W,
    const float* __restrict__ pe, const float* __restrict__ bvec,
    float* __restrict__ C)
{
    __shared__ float As[64 * 65];
    __shared__ float Bs[64 * 65];
    const int tid  = threadIdx.x;
    const int row0 = blockIdx.x * 64;
    const int col0 = blockIdx.y * 64;
    const int tx = tid & 15, ty = tid >> 4;

    float acc[4][4] = {};

#pragma unroll
    for (int kc = 0; kc < KTOT / 64; ++kc) {
#pragma unroll
        for (int it = 0; it < 16; ++it) {            // 64x64 elems / 256 thr
            int l = tid + it * 256;
            int r = l >> 6, k = l & 63;
            float v = A[(size_t)(row0 + r) * KTOT + kc * 64 + k];
            if (PE) v += pe[r * 128 + kc * 64 + k];  // token%64 == r (tiles align)
            As[r * 65 + k] = v;
            Bs[r * 65 + k] = W[(size_t)(col0 + r) * KTOT + kc * 64 + k];
        }
        __syncthreads();
#pragma unroll 8
        for (int k = 0; k < 64; ++k) {
            float a[4], b[4];
#pragma unroll
            for (int i = 0; i < 4; ++i) a[i] = As[(ty + 16 * i) * 65 + k];
#pragma unroll
            for (int j = 0; j < 4; ++j) b[j] = Bs[(tx + 16 * j) * 65 + k];
#pragma unroll
            for (int i = 0; i < 4; ++i)
#pragma unroll
                for (int j = 0; j < 4; ++j) acc[i][j] += a[i] * b[j];
        }
        __syncthreads();
    }

#pragma unroll
    for (int i = 0; i < 4; ++i) {
        int rr = row0 + ty + 16 * i;
#pragma unroll
        for (int j = 0; j < 4; ++j) {
            int cc = col0 + tx + 16 * j;
            float v = acc[i][j];
            if (BIAS) v += bvec[cc];
            C[(size_t)rr * LDC + cc] = v;
        }
    }
}

// ---------------- self attention (flash-style, one query per thread) -------
// grid (WB, NHEADS), block 128
__global__ void __launch_bounds__(128) attn_self(const float* __restrict__ mask)
{
    const int b = blockIdx.x, h = blockIdx.y, i = threadIdx.x;
    __shared__ float ks[NTOK * HD];
    __shared__ float vs[NTOK * HD];
    const float* base = g_qkv_self + (size_t)b * NTOK * 384;

    {   // stage K,V rows (this thread's token) into smem
        const float4* kr = (const float4*)(base + i * 384 + 128 + h * HD);
        float4* kd = (float4*)(ks + i * HD);
        kd[0] = kr[0]; kd[1] = kr[1]; kd[2] = kr[2]; kd[3] = kr[3];
        const float4* vr = (const float4*)(base + i * 384 + 256 + h * HD);
        float4* vd = (float4*)(vs + i * HD);
        vd[0] = vr[0]; vd[1] = vr[1]; vd[2] = vr[2]; vd[3] = vr[3];
    }
    float q[HD];
    const float* qr = base + i * 384 + h * HD;
#pragma unroll
    for (int c = 0; c < HD; ++c) q[c] = qr[c] * 0.25f;   // SCALE = 16^-0.5
    __syncthreads();

    const float* mrow = mask + (size_t)(b & 511) * 16384 + i * 128;
    const float* brow = g_bias + h * 16384 + i * 128;

    float mx = -1e30f, sm = 0.f, acc[HD] = {};
#pragma unroll 4
    for (int m = 0; m < NTOK; ++m) {
        const float* kk = ks + m * HD;
        float s = 0.f;
#pragma unroll
        for (int c = 0; c < HD; ++c) s += q[c] * kk[c];
        s += brow[m] + mrow[m];
        if (s > mx) {
            float corr = __expf(mx - s);
            sm *= corr;
#pragma unroll
            for (int c = 0; c < HD; ++c) acc[c] *= corr;
            mx = s;
        }
        float p = __expf(s - mx);
        sm += p;
        const float* vv = vs + m * HD;
#pragma unroll
        for (int c = 0; c < HD; ++c) acc[c] += p * vv[c];
    }
    float inv = 1.f / sm;
    float* orow = g_concat + (size_t)b * NTOK * 256 + i * 256 + 128 + h * HD;
#pragma unroll
    for (int c = 0; c < HD; ++c) orow[c] = acc[c] * inv;
}

// ---------------- mutual cross attention (two 64x64 halves per block) ------
// thread i<64:  out token i    = query(64+i) over keys[0:64)   (frame2 -> frame1)
// thread i>=64: out token i    = query(i-64) over keys[64:128) (frame1 -> frame2)
__global__ void __launch_bounds__(128) attn_mut(const float* __restrict__ mask)
{
    const int b = blockIdx.x, h = blockIdx.y, i = threadIdx.x;
    __shared__ float ks[NTOK * HD];
    __shared__ float vs[NTOK * HD];
    const float* base = g_qkv_mut + (size_t)b * NTOK * 384;

    {
        const float4* kr = (const float4*)(base + i * 384 + 128 + h * HD);
        float4* kd = (float4*)(ks + i * HD);
        kd[0] = kr[0]; kd[1] = kr[1]; kd[2] = kr[2]; kd[3] = kr[3];
        const float4* vr = (const float4*)(base + i * 384 + 256 + h * HD);
        float4* vd = (float4*)(vs + i * HD);
        vd[0] = vr[0]; vd[1] = vr[1]; vd[2] = vr[2]; vd[3] = vr[3];
    }
    const int qrow = (i < 64) ? (64 + i) : (i - 64);
    const int il   = (i < 64) ? i : (i - 64);
    const int kb   = (i < 64) ? 0 : 64;
    float q[HD];
    const float* qr = base + qrow * 384 + h * HD;
#pragma unroll
    for (int c = 0; c < HD; ++c) q[c] = qr[c] * 0.25f;
    __syncthreads();

    const float* mrow = mask + (size_t)(b & 511) * 16384 + il * 128; // mask[:, :64, :64]

    float mx = -1e30f, sm = 0.f, acc[HD] = {};
#pragma unroll 4
    for (int m = 0; m < 64; ++m) {
        const float* kk = ks + (kb + m) * HD;
        float s = 0.f;
#pragma unroll
        for (int c = 0; c < HD; ++c) s += q[c] * kk[c];
        s += mrow[m];
        if (s > mx) {
            float corr = __expf(mx - s);
            sm *= corr;
#pragma unroll
            for (int c = 0; c < HD; ++c) acc[c] *= corr;
            mx = s;
        }
        float p = __expf(s - mx);
        sm += p;
        const float* vv = vs + (kb + m) * HD;
#pragma unroll
        for (int c = 0; c < HD; ++c) acc[c] += p * vv[c];
    }
    float inv = 1.f / sm;
    float* orow = g_concat + (size_t)b * NTOK * 256 + i * 256 + h * HD; // first half
#pragma unroll
    for (int c = 0; c < HD; ++c) orow[c] = acc[c] * inv;
}

// ---------------- launch ----------------------------------------------------
extern "C" void kernel_launch(void* const* d_in, const int* in_sizes, int n_in,
                              void* d_out, int out_size)
{
    const float* x         = (const float*)d_in[0];   // [1024,128,128]
    const float* mask      = (const float*)d_in[1];   // [512,128,128]
    const float* w_self    = (const float*)d_in[2];   // [384,128]
    const float* w_mut     = (const float*)d_in[3];   // [384,128]
    const float* w_proj    = (const float*)d_in[4];   // [128,256]
    const float* b_proj    = (const float*)d_in[5];   // [128]
    const float* rpe_table = (const float*)d_in[6];   // [675,8]
    const float* pe        = (const float*)d_in[7];   // [1,64,128]
    const int*   rpe_index = (const int*)d_in[8];     // [128,128]
    float* out = (float*)d_out;

    float *qs, *qm, *cc;
    cudaGetSymbolAddress((void**)&qs, g_qkv_self);
    cudaGetSymbolAddress((void**)&qm, g_qkv_mut);
    cudaGetSymbolAddress((void**)&cc, g_concat);

    bias_prep<<<64, 256>>>(rpe_index, rpe_table);

    // QKV GEMMs: M = 1024*128 = 131072 rows, N = 384, K = 128
    gemm64<128, 384, false, false><<<dim3(2048, 6), 256>>>(x, w_self, nullptr, nullptr, qs);
    gemm64<128, 384, true,  false><<<dim3(2048, 6), 256>>>(x, w_mut,  pe,      nullptr, qm);

    attn_self<<<dim3(WB, NHEADS), 128>>>(mask);
    attn_mut <<<dim3(WB, NHEADS), 128>>>(mask);

    // projection: [131072,256] @ [128,256]^T + b
    gemm64<256, 128, false, true><<<dim3(2048, 2), 256>>>(cc, w_proj, nullptr, b_proj, out);
}

// round 4
// speedup vs baseline: 2.3186x; 2.3186x over previous
#include <cuda_runtime.h>
#include <cuda_bf16.h>
#include <cstddef>

#define WB     1024
#define NTOK   128
#define NHEADS 8
#define HD     16
#define MROWS  (WB * NTOK)          // 131072

// ---------------- scratch (device globals; no runtime allocation) ----------
// 3-term split: A-side triplets (ah, ah, al); B-side triplets (bh, bl, bh).
__device__ unsigned short g_xs3  [(size_t)MROWS * 384];   // x,   K'=384
__device__ unsigned short g_xpes3[(size_t)MROWS * 384];   // x+pe K'=384
__device__ unsigned short g_ws3  [384 * 384];             // w_self
__device__ unsigned short g_wm3  [384 * 384];             // w_mut
__device__ unsigned short g_wp3  [128 * 768];             // w_proj K'=768
__device__ float g_qkv_self[(size_t)MROWS * 384];
__device__ float g_qkv_mut [(size_t)MROWS * 384];
__device__ unsigned short g_concat3[(size_t)MROWS * 768]; // [row][col*3]
__device__ float g_biasT[NHEADS * NTOK * NTOK];           // [h][m][i]
__device__ float g_maskT[512 * NTOK * NTOK];              // [w][m][i]

__device__ __forceinline__ void split_hl(float v, unsigned short& h, unsigned short& l) {
    __nv_bfloat16 hh = __float2bfloat16(v);
    float r = v - __bfloat162float(hh);
    __nv_bfloat16 ll = __float2bfloat16(r);
    h = *(unsigned short*)&hh;
    l = *(unsigned short*)&ll;
}

// ---------------- prep kernels ---------------------------------------------
// B-side weight split: triplet (h, l, h)
__global__ void wsplitB(const float* __restrict__ src, unsigned short* __restrict__ dst, int n)
{
    int i = blockIdx.x * 256 + threadIdx.x;
    if (i < n) {
        unsigned short h, l;
        split_hl(src[i], h, l);
        dst[3 * i] = h; dst[3 * i + 1] = l; dst[3 * i + 2] = h;
    }
}

// A-side x split: triplet (h, h, l). 8 elements per thread, vector stores.
__global__ void xprep(const float* __restrict__ x, const float* __restrict__ pe)
{
    size_t idx8 = (size_t)blockIdx.x * 256 + threadIdx.x;   // 0..2097151
    size_t e0 = idx8 * 8;
    int c = (int)(e0 & 127);
    int t = (int)((e0 >> 7) & 127);
    float4 xv0 = ((const float4*)x)[idx8 * 2];
    float4 xv1 = ((const float4*)x)[idx8 * 2 + 1];
    const float* pp = pe + (t & 63) * 128 + c;
    float xe[8] = {xv0.x, xv0.y, xv0.z, xv0.w, xv1.x, xv1.y, xv1.z, xv1.w};

    unsigned short b0[24], b1[24];
#pragma unroll
    for (int j = 0; j < 8; ++j) {
        unsigned short h, l;
        split_hl(xe[j], h, l);
        b0[3 * j] = h; b0[3 * j + 1] = h; b0[3 * j + 2] = l;
        split_hl(xe[j] + pp[j], h, l);
        b1[3 * j] = h; b1[3 * j + 1] = h; b1[3 * j + 2] = l;
    }
    uint4* d0 = (uint4*)(g_xs3 + 3 * e0);
    uint4* d1 = (uint4*)(g_xpes3 + 3 * e0);
    const uint4* s0 = (const uint4*)b0;
    const uint4* s1 = (const uint4*)b1;
    d0[0] = s0[0]; d0[1] = s0[1]; d0[2] = s0[2];
    d1[0] = s1[0]; d1[1] = s1[1]; d1[2] = s1[2];
}

__global__ void biasT_prep(const int* __restrict__ rpe_index, const float* __restrict__ rpe_table)
{
    int tid = blockIdx.x * 256 + threadIdx.x;       // tid = m*128 + i
    int i = tid & 127, m = tid >> 7;
    int t = rpe_index[i * 128 + m];
#pragma unroll
    for (int h = 0; h < NHEADS; ++h)
        g_biasT[h * 16384 + tid] = rpe_table[t * NHEADS + h];
}

__global__ void maskT_prep(const float* __restrict__ mask)
{
    __shared__ float tile[32][33];
    int w = blockIdx.z;
    int x0 = blockIdx.x * 32, y0 = blockIdx.y * 32;
    int tx = threadIdx.x, ty = threadIdx.y;         // 32 x 8
    const float* src = mask + (size_t)w * 16384;
    float* dst = g_maskT + (size_t)w * 16384;
#pragma unroll
    for (int j = 0; j < 32; j += 8)
        tile[ty + j][tx] = src[(y0 + ty + j) * 128 + x0 + tx];
    __syncthreads();
#pragma unroll
    for (int j = 0; j < 32; j += 8)
        dst[(x0 + ty + j) * 128 + y0 + tx] = tile[tx][ty + j];
}

// ---------------- bf16-split tensor-core GEMM ------------------------------
// block tile 128x64, 8 warps (4x2), warp tile 32x32, k-chunk 64
#define MMA_BF16(d, a, b) \
    asm volatile("mma.sync.aligned.m16n8k16.row.col.f32.bf16.bf16.f32 " \
        "{%0,%1,%2,%3},{%4,%5,%6,%7},{%8,%9},{%0,%1,%2,%3};" \
        : "+f"(d[0]), "+f"(d[1]), "+f"(d[2]), "+f"(d[3]) \
        : "r"(a[0]), "r"(a[1]), "r"(a[2]), "r"(a[3]), "r"(b[0]), "r"(b[1]))

template<int KTOT, int NTOT, bool BIAS>
__global__ void __launch_bounds__(256) gemm_bf16(
    const __nv_bfloat16* __restrict__ A, const __nv_bfloat16* __restrict__ W,
    const float* __restrict__ bvec, float* __restrict__ C)
{
    __shared__ __nv_bfloat16 As[128 * 72];
    __shared__ __nv_bfloat16 Bs[64 * 72];
    const int tid = threadIdx.x;
    const int lane = tid & 31, wid = tid >> 5;
    const int wm = (wid & 3) * 32, wn = (wid >> 2) * 32;
    const int g = lane >> 2, tg = lane & 3;
    const size_t row0 = (size_t)blockIdx.x * 128;
    const int col0 = blockIdx.y * 64;

    float acc[2][4][4];
#pragma unroll
    for (int i = 0; i < 2; ++i)
#pragma unroll
        for (int j = 0; j < 4; ++j)
#pragma unroll
            for (int k = 0; k < 4; ++k) acc[i][j][k] = 0.f;

    for (int kc = 0; kc < KTOT / 64; ++kc) {
#pragma unroll
        for (int it = 0; it < 4; ++it) {
            int l = tid + it * 256;
            int r = l >> 3, u = l & 7;
            *(uint4*)&As[r * 72 + u * 8] =
                *(const uint4*)&A[(row0 + r) * KTOT + kc * 64 + u * 8];
        }
#pragma unroll
        for (int it = 0; it < 2; ++it) {
            int l = tid + it * 256;
            int r = l >> 3, u = l & 7;
            *(uint4*)&Bs[r * 72 + u * 8] =
                *(const uint4*)&W[(size_t)(col0 + r) * KTOT + kc * 64 + u * 8];
        }
        __syncthreads();
#pragma unroll
        for (int ks = 0; ks < 4; ++ks) {
            const int kb = ks * 16;
            unsigned a[2][4], b[4][2];
#pragma unroll
            for (int mt = 0; mt < 2; ++mt) {
                int rb = wm + mt * 16;
                a[mt][0] = *(const unsigned*)&As[(rb + g)     * 72 + kb + 2 * tg];
                a[mt][1] = *(const unsigned*)&As[(rb + g + 8) * 72 + kb + 2 * tg];
                a[mt][2] = *(const unsigned*)&As[(rb + g)     * 72 + kb + 2 * tg + 8];
                a[mt][3] = *(const unsigned*)&As[(rb + g + 8) * 72 + kb + 2 * tg + 8];
            }
#pragma unroll
            for (int nt = 0; nt < 4; ++nt) {
                int nr = wn + nt * 8 + g;
                b[nt][0] = *(const unsigned*)&Bs[nr * 72 + kb + 2 * tg];
                b[nt][1] = *(const unsigned*)&Bs[nr * 72 + kb + 2 * tg + 8];
            }
#pragma unroll
            for (int mt = 0; mt < 2; ++mt)
#pragma unroll
                for (int nt = 0; nt < 4; ++nt)
                    MMA_BF16(acc[mt][nt], a[mt], b[nt]);
        }
        __syncthreads();
    }

#pragma unroll
    for (int mt = 0; mt < 2; ++mt) {
#pragma unroll
        for (int nt = 0; nt < 4; ++nt) {
            size_t row = row0 + wm + mt * 16 + g;
            int col = col0 + wn + nt * 8 + 2 * tg;
            float b0 = BIAS ? bvec[col] : 0.f, b1 = BIAS ? bvec[col + 1] : 0.f;
            *(float2*)&C[row * NTOT + col] =
                make_float2(acc[mt][nt][0] + b0, acc[mt][nt][1] + b1);
            *(float2*)&C[(row + 8) * NTOT + col] =
                make_float2(acc[mt][nt][2] + b0, acc[mt][nt][3] + b1);
        }
    }
}

// ---------------- write attention output as A-side triplets -----------------
__device__ __forceinline__ void store_triplets16(unsigned short* dst, const float* v)
{
    unsigned short ob[48];
#pragma unroll
    for (int c = 0; c < 16; ++c) {
        unsigned short h, l;
        split_hl(v[c], h, l);
        ob[3 * c] = h; ob[3 * c + 1] = h; ob[3 * c + 2] = l;
    }
    uint4* d = (uint4*)dst;
    const uint4* s = (const uint4*)ob;
#pragma unroll
    for (int j = 0; j < 6; ++j) d[j] = s[j];
}

// ---------------- self attention -------------------------------------------
__global__ void __launch_bounds__(128) attn_self()
{
    const int b = blockIdx.x, h = blockIdx.y, i = threadIdx.x;
    __shared__ float ks[NTOK * HD];
    __shared__ float vs[NTOK * HD];
    const float* base = g_qkv_self + (size_t)b * NTOK * 384;
    {
        const float4* kr = (const float4*)(base + i * 384 + 128 + h * HD);
        float4* kd = (float4*)(ks + i * HD);
        kd[0] = kr[0]; kd[1] = kr[1]; kd[2] = kr[2]; kd[3] = kr[3];
        const float4* vr = (const float4*)(base + i * 384 + 256 + h * HD);
        float4* vd = (float4*)(vs + i * HD);
        vd[0] = vr[0]; vd[1] = vr[1]; vd[2] = vr[2]; vd[3] = vr[3];
    }
    float q[HD];
    const float* qr = base + i * 384 + h * HD;
#pragma unroll
    for (int c = 0; c < HD; ++c) q[c] = qr[c] * 0.25f;
    __syncthreads();

    const float* mcol = g_maskT + (size_t)(b & 511) * 16384 + i;
    const float* bcol = g_biasT + h * 16384 + i;

    float mx = -1e30f, sm = 0.f, acc[HD] = {};
#pragma unroll 4
    for (int m = 0; m < NTOK; ++m) {
        const float4* kk = (const float4*)(ks + m * HD);
        float4 k0 = kk[0], k1 = kk[1], k2 = kk[2], k3 = kk[3];
        float s = mcol[m * 128] + bcol[m * 128];
        s += q[0]*k0.x + q[1]*k0.y + q[2]*k0.z + q[3]*k0.w;
        s += q[4]*k1.x + q[5]*k1.y + q[6]*k1.z + q[7]*k1.w;
        s += q[8]*k2.x + q[9]*k2.y + q[10]*k2.z + q[11]*k2.w;
        s += q[12]*k3.x + q[13]*k3.y + q[14]*k3.z + q[15]*k3.w;
        if (s > mx) {
            float corr = __expf(mx - s);
            sm *= corr;
#pragma unroll
            for (int c = 0; c < HD; ++c) acc[c] *= corr;
            mx = s;
        }
        float p = __expf(s - mx);
        sm += p;
        const float4* vv = (const float4*)(vs + m * HD);
        float4 v0 = vv[0], v1 = vv[1], v2 = vv[2], v3 = vv[3];
        acc[0] += p*v0.x; acc[1] += p*v0.y; acc[2]  += p*v0.z; acc[3]  += p*v0.w;
        acc[4] += p*v1.x; acc[5] += p*v1.y; acc[6]  += p*v1.z; acc[7]  += p*v1.w;
        acc[8] += p*v2.x; acc[9] += p*v2.y; acc[10] += p*v2.z; acc[11] += p*v2.w;
        acc[12]+= p*v3.x; acc[13]+= p*v3.y; acc[14] += p*v3.z; acc[15] += p*v3.w;
    }
    float inv = 1.f / sm;
    float o[HD];
#pragma unroll
    for (int c = 0; c < HD; ++c) o[c] = acc[c] * inv;
    store_triplets16(g_concat3 + ((size_t)b * NTOK + i) * 768 + (128 + h * HD) * 3, o);
}

// ---------------- mutual cross attention -----------------------------------
__global__ void __launch_bounds__(128) attn_mut()
{
    const int b = blockIdx.x, h = blockIdx.y, i = threadIdx.x;
    __shared__ float ks[NTOK * HD];
    __shared__ float vs[NTOK * HD];
    const float* base = g_qkv_mut + (size_t)b * NTOK * 384;
    {
        const float4* kr = (const float4*)(base + i * 384 + 128 + h * HD);
        float4* kd = (float4*)(ks + i * HD);
        kd[0] = kr[0]; kd[1] = kr[1]; kd[2] = kr[2]; kd[3] = kr[3];
        const float4* vr = (const float4*)(base + i * 384 + 256 + h * HD);
        float4* vd = (float4*)(vs + i * HD);
        vd[0] = vr[0]; vd[1] = vr[1]; vd[2] = vr[2]; vd[3] = vr[3];
    }
    const int qrow = (i < 64) ? (64 + i) : (i - 64);
    const int il   = (i < 64) ? i : (i - 64);
    const int kb   = (i < 64) ? 0 : 64;
    float q[HD];
    const float* qr = base + qrow * 384 + h * HD;
#pragma unroll
    for (int c = 0; c < HD; ++c) q[c] = qr[c] * 0.25f;
    __syncthreads();

    const float* mcol = g_maskT + (size_t)(b & 511) * 16384 + il;

    float mx = -1e30f, sm = 0.f, acc[HD] = {};
#pragma unroll 4
    for (int m = 0; m < 64; ++m) {
        const float4* kk = (const float4*)(ks + (kb + m) * HD);
        float4 k0 = kk[0], k1 = kk[1], k2 = kk[2], k3 = kk[3];
        float s = mcol[m * 128];
        s += q[0]*k0.x + q[1]*k0.y + q[2]*k0.z + q[3]*k0.w;
        s += q[4]*k1.x + q[5]*k1.y + q[6]*k1.z + q[7]*k1.w;
        s += q[8]*k2.x + q[9]*k2.y + q[10]*k2.z + q[11]*k2.w;
        s += q[12]*k3.x + q[13]*k3.y + q[14]*k3.z + q[15]*k3.w;
        if (s > mx) {
            float corr = __expf(mx - s);
            sm *= corr;
#pragma unroll
            for (int c = 0; c < HD; ++c) acc[c] *= corr;
            mx = s;
        }
        float p = __expf(s - mx);
        sm += p;
        const float4* vv = (const float4*)(vs + (kb + m) * HD);
        float4 v0 = vv[0], v1 = vv[1], v2 = vv[2], v3 = vv[3];
        acc[0] += p*v0.x; acc[1] += p*v0.y; acc[2]  += p*v0.z; acc[3]  += p*v0.w;
        acc[4] += p*v1.x; acc[5] += p*v1.y; acc[6]  += p*v1.z; acc[7]  += p*v1.w;
        acc[8] += p*v2.x; acc[9] += p*v2.y; acc[10] += p*v2.z; acc[11] += p*v2.w;
        acc[12]+= p*v3.x; acc[13]+= p*v3.y; acc[14] += p*v3.z; acc[15] += p*v3.w;
    }
    float inv = 1.f / sm;
    float o[HD];
#pragma unroll
    for (int c = 0; c < HD; ++c) o[c] = acc[c] * inv;
    store_triplets16(g_concat3 + ((size_t)b * NTOK + i) * 768 + (h * HD) * 3, o);
}

// ---------------- launch ----------------------------------------------------
extern "C" void kernel_launch(void* const* d_in, const int* in_sizes, int n_in,
                              void* d_out, int out_size)
{
    const float* x         = (const float*)d_in[0];
    const float* mask      = (const float*)d_in[1];
    const float* w_self    = (const float*)d_in[2];
    const float* w_mut     = (const float*)d_in[3];
    const float* w_proj    = (const float*)d_in[4];
    const float* b_proj    = (const float*)d_in[5];
    const float* rpe_table = (const float*)d_in[6];
    const float* pe        = (const float*)d_in[7];
    const int*   rpe_index = (const int*)d_in[8];
    float* out = (float*)d_out;

    unsigned short *ws, *wm, *wp, *xs, *xpes, *cc;
    float *qs, *qm;
    cudaGetSymbolAddress((void**)&ws, g_ws3);
    cudaGetSymbolAddress((void**)&wm, g_wm3);
    cudaGetSymbolAddress((void**)&wp, g_wp3);
    cudaGetSymbolAddress((void**)&xs, g_xs3);
    cudaGetSymbolAddress((void**)&xpes, g_xpes3);
    cudaGetSymbolAddress((void**)&qs, g_qkv_self);
    cudaGetSymbolAddress((void**)&qm, g_qkv_mut);
    cudaGetSymbolAddress((void**)&cc, g_concat3);

    // prep
    wsplitB<<<(384 * 128 + 255) / 256, 256>>>(w_self, ws, 384 * 128);
    wsplitB<<<(384 * 128 + 255) / 256, 256>>>(w_mut,  wm, 384 * 128);
    wsplitB<<<(128 * 256 + 255) / 256, 256>>>(w_proj, wp, 128 * 256);
    xprep<<<MROWS * 128 / 8 / 256, 256>>>(x, pe);
    biasT_prep<<<64, 256>>>(rpe_index, rpe_table);
    maskT_prep<<<dim3(4, 4, 512), dim3(32, 8)>>>(mask);

    // QKV GEMMs (K' = 384)
    gemm_bf16<384, 384, false><<<dim3(1024, 6), 256>>>(
        (const __nv_bfloat16*)xs,   (const __nv_bfloat16*)ws, nullptr, qs);
    gemm_bf16<384, 384, false><<<dim3(1024, 6), 256>>>(
        (const __nv_bfloat16*)xpes, (const __nv_bfloat16*)wm, nullptr, qm);

    // attention
    attn_self<<<dim3(WB, NHEADS), 128>>>();
    attn_mut <<<dim3(WB, NHEADS), 128>>>();

    // projection (K' = 768)
    gemm_bf16<768, 128, true><<<dim3(1024, 2), 256>>>(
        (const __nv_bfloat16*)cc, (const __nv_bfloat16*)wp, b_proj, out);
}

// round 5
// speedup vs baseline: 2.3459x; 1.0118x over previous
#include <cuda_runtime.h>
#include <cuda_bf16.h>
#include <cstddef>
#include <cstdint>

#define WB     1024
#define NTOK   128
#define NHEADS 8
#define HD     16
#define MROWS  (WB * NTOK)          // 131072

// ---------------- scratch (device globals; no runtime allocation) ----------
// 3-term split: A-side triplets (ah, ah, al); B-side triplets (bh, bl, bh).
__device__ unsigned short g_xs3  [(size_t)MROWS * 384];   // x,   K'=384
__device__ unsigned short g_xpes3[(size_t)MROWS * 384];   // x+pe K'=384
__device__ unsigned short g_ws3  [384 * 384];             // w_self
__device__ unsigned short g_wm3  [384 * 384];             // w_mut
__device__ unsigned short g_wp3  [128 * 768];             // w_proj K'=768
__device__ float g_qkv_self[(size_t)MROWS * 384];
__device__ float g_qkv_mut [(size_t)MROWS * 384];
__device__ unsigned short g_concat3[(size_t)MROWS * 768]; // [row][col*3]
__device__ float g_biasT[NHEADS * NTOK * NTOK];           // [h][m][i]
__device__ float g_maskT[512 * NTOK * NTOK];              // [w][m][i]

__device__ __forceinline__ void split_hl(float v, unsigned short& h, unsigned short& l) {
    __nv_bfloat16 hh = __float2bfloat16(v);
    float r = v - __bfloat162float(hh);
    __nv_bfloat16 ll = __float2bfloat16(r);
    h = *(unsigned short*)&hh;
    l = *(unsigned short*)&ll;
}

// ---------------- prep kernels ---------------------------------------------
// all three weights split B-side (h, l, h) in one launch
__global__ void wsplit_all(const float* __restrict__ ws, const float* __restrict__ wm,
                           const float* __restrict__ wp)
{
    int i = blockIdx.x * 256 + threadIdx.x;     // 0 .. 131071
    float v; unsigned short* dst;
    if (i < 49152)       { v = ws[i];          dst = g_ws3 + 3 * i; }
    else if (i < 98304)  { v = wm[i - 49152];  dst = g_wm3 + 3 * (i - 49152); }
    else                 { v = wp[i - 98304];  dst = g_wp3 + 3 * (i - 98304); }
    unsigned short h, l;
    split_hl(v, h, l);
    dst[0] = h; dst[1] = l; dst[2] = h;
}

// A-side x split: triplet (h, h, l). 8 elements per thread, vector stores.
__global__ void xprep(const float* __restrict__ x, const float* __restrict__ pe)
{
    size_t idx8 = (size_t)blockIdx.x * 256 + threadIdx.x;
    size_t e0 = idx8 * 8;
    int c = (int)(e0 & 127);
    int t = (int)((e0 >> 7) & 127);
    float4 xv0 = ((const float4*)x)[idx8 * 2];
    float4 xv1 = ((const float4*)x)[idx8 * 2 + 1];
    const float* pp = pe + (t & 63) * 128 + c;
    float xe[8] = {xv0.x, xv0.y, xv0.z, xv0.w, xv1.x, xv1.y, xv1.z, xv1.w};

    unsigned short b0[24], b1[24];
#pragma unroll
    for (int j = 0; j < 8; ++j) {
        unsigned short h, l;
        split_hl(xe[j], h, l);
        b0[3 * j] = h; b0[3 * j + 1] = h; b0[3 * j + 2] = l;
        split_hl(xe[j] + pp[j], h, l);
        b1[3 * j] = h; b1[3 * j + 1] = h; b1[3 * j + 2] = l;
    }
    uint4* d0 = (uint4*)(g_xs3 + 3 * e0);
    uint4* d1 = (uint4*)(g_xpes3 + 3 * e0);
    const uint4* s0 = (const uint4*)b0;
    const uint4* s1 = (const uint4*)b1;
    d0[0] = s0[0]; d0[1] = s0[1]; d0[2] = s0[2];
    d1[0] = s1[0]; d1[1] = s1[1]; d1[2] = s1[2];
}

__global__ void biasT_prep(const int* __restrict__ rpe_index, const float* __restrict__ rpe_table)
{
    int tid = blockIdx.x * 256 + threadIdx.x;       // tid = m*128 + i
    int i = tid & 127, m = tid >> 7;
    int t = rpe_index[i * 128 + m];
#pragma unroll
    for (int h = 0; h < NHEADS; ++h)
        g_biasT[h * 16384 + tid] = rpe_table[t * NHEADS + h];
}

__global__ void maskT_prep(const float* __restrict__ mask)
{
    __shared__ float tile[32][33];
    int w = blockIdx.z;
    int x0 = blockIdx.x * 32, y0 = blockIdx.y * 32;
    int tx = threadIdx.x, ty = threadIdx.y;         // 32 x 8
    const float* src = mask + (size_t)w * 16384;
    float* dst = g_maskT + (size_t)w * 16384;
#pragma unroll
    for (int j = 0; j < 32; j += 8)
        tile[ty + j][tx] = src[(y0 + ty + j) * 128 + x0 + tx];
    __syncthreads();
#pragma unroll
    for (int j = 0; j < 32; j += 8)
        dst[(x0 + ty + j) * 128 + y0 + tx] = tile[tx][ty + j];
}

// ---------------- bf16-split tensor-core GEMM ------------------------------
// block tile 128x128, 8 warps (2m x 4n), warp tile 64x32, k-chunk 64,
// 2-stage cp.async pipeline, ldmatrix fragment loads.
#define MMA_BF16(d, a, b0r, b1r) \
    asm volatile("mma.sync.aligned.m16n8k16.row.col.f32.bf16.bf16.f32 " \
        "{%0,%1,%2,%3},{%4,%5,%6,%7},{%8,%9},{%0,%1,%2,%3};" \
        : "+f"(d[0]), "+f"(d[1]), "+f"(d[2]), "+f"(d[3]) \
        : "r"(a[0]), "r"(a[1]), "r"(a[2]), "r"(a[3]), "r"(b0r), "r"(b1r))

#define LDSM4(r0, r1, r2, r3, addr) \
    asm volatile("ldmatrix.sync.aligned.m8n8.x4.shared.b16 {%0,%1,%2,%3}, [%4];" \
        : "=r"(r0), "=r"(r1), "=r"(r2), "=r"(r3) : "r"(addr))

#define CP16(dst, src) \
    asm volatile("cp.async.cg.shared.global [%0], [%1], 16;" :: "r"(dst), "l"(src))

#define PITCH 72
#define STAGE_ELEMS (128 * PITCH)

template<int KTOT, int NTOT, bool BIAS>
__global__ void __launch_bounds__(256) gemm_bf16(
    const __nv_bfloat16* __restrict__ A, const __nv_bfloat16* __restrict__ W,
    const float* __restrict__ bvec, float* __restrict__ C)
{
    extern __shared__ __nv_bfloat16 smem[];
    __nv_bfloat16* As = smem;                        // [2][128*72]
    __nv_bfloat16* Bs = smem + 2 * STAGE_ELEMS;      // [2][128*72]

    const int tid = threadIdx.x;
    const int lane = tid & 31, wid = tid >> 5;
    const int wm = (wid & 1) * 64, wn = (wid >> 1) * 32;
    const int g = lane >> 2, tg = lane & 3;
    const size_t row0 = (size_t)blockIdx.y * 128;
    const int col0 = blockIdx.x * 128;
    constexpr int NC = KTOT / 64;

    // per-thread cp.async source/dest indices (4 x 16B for A, 4 x 16B for B)
    const int ldr = tid >> 1;                        // 0..127 row
    const int ldu = (tid & 1) * 4;                   // 16B-chunk pair start

    float acc[4][4][4] = {};

    // ldmatrix addresses (constant across stages except stage base)
    const int a_row = wm + (lane & 15);
    const int a_col = (lane >> 4) * 8;
    const int bq = lane >> 3;
    const int b_row = wn + ((bq >> 1) * 8) + (lane & 7);
    const int b_col = (bq & 1) * 8;

#define LOAD_STAGE(kc, s)                                                        \
    {                                                                            \
        const __nv_bfloat16* Ab = A + (row0 + ldr) * KTOT + (kc) * 64;           \
        const __nv_bfloat16* Wb = W + (size_t)(col0 + ldr) * KTOT + (kc) * 64;   \
        __nv_bfloat16* Ad = As + (s) * STAGE_ELEMS + ldr * PITCH;                \
        __nv_bfloat16* Bd = Bs + (s) * STAGE_ELEMS + ldr * PITCH;                \
        _Pragma("unroll")                                                        \
        for (int u = 0; u < 4; ++u) {                                            \
            unsigned da = (unsigned)__cvta_generic_to_shared(Ad + (ldu + u) * 8);\
            CP16(da, Ab + (ldu + u) * 8);                                        \
            unsigned db = (unsigned)__cvta_generic_to_shared(Bd + (ldu + u) * 8);\
            CP16(db, Wb + (ldu + u) * 8);                                        \
        }                                                                        \
        asm volatile("cp.async.commit_group;");                                  \
    }

    LOAD_STAGE(0, 0);

    for (int kc = 0; kc < NC; ++kc) {
        if (kc + 1 < NC) {
            LOAD_STAGE(kc + 1, (kc + 1) & 1);
            asm volatile("cp.async.wait_group 1;");
        } else {
            asm volatile("cp.async.wait_group 0;");
        }
        __syncthreads();

        const __nv_bfloat16* Ad = As + (kc & 1) * STAGE_ELEMS;
        const __nv_bfloat16* Bd = Bs + (kc & 1) * STAGE_ELEMS;
#pragma unroll
        for (int ks = 0; ks < 4; ++ks) {
            const int kb = ks * 16;
            uint32_t a[4][4], b[2][4];
#pragma unroll
            for (int mt = 0; mt < 4; ++mt) {
                unsigned ad = (unsigned)__cvta_generic_to_shared(
                    Ad + (a_row + mt * 16) * PITCH + kb + a_col);
                LDSM4(a[mt][0], a[mt][1], a[mt][2], a[mt][3], ad);
            }
#pragma unroll
            for (int p = 0; p < 2; ++p) {
                unsigned bd = (unsigned)__cvta_generic_to_shared(
                    Bd + (b_row + p * 16) * PITCH + kb + b_col);
                LDSM4(b[p][0], b[p][1], b[p][2], b[p][3], bd);
            }
#pragma unroll
            for (int mt = 0; mt < 4; ++mt)
#pragma unroll
                for (int nt = 0; nt < 4; ++nt)
                    MMA_BF16(acc[mt][nt], a[mt], b[nt >> 1][(nt & 1) * 2],
                             b[nt >> 1][(nt & 1) * 2 + 1]);
        }
        __syncthreads();
    }

#pragma unroll
    for (int mt = 0; mt < 4; ++mt) {
#pragma unroll
        for (int nt = 0; nt < 4; ++nt) {
            size_t row = row0 + wm + mt * 16 + g;
            int col = col0 + wn + nt * 8 + 2 * tg;
            float b0 = BIAS ? bvec[col] : 0.f, b1 = BIAS ? bvec[col + 1] : 0.f;
            *(float2*)&C[row * NTOT + col] =
                make_float2(acc[mt][nt][0] + b0, acc[mt][nt][1] + b1);
            *(float2*)&C[(row + 8) * NTOT + col] =
                make_float2(acc[mt][nt][2] + b0, acc[mt][nt][3] + b1);
        }
    }
}

// ---------------- write attention output as A-side triplets -----------------
__device__ __forceinline__ void store_triplets16(unsigned short* dst, const float* v)
{
    unsigned short ob[48];
#pragma unroll
    for (int c = 0; c < 16; ++c) {
        unsigned short h, l;
        split_hl(v[c], h, l);
        ob[3 * c] = h; ob[3 * c + 1] = h; ob[3 * c + 2] = l;
    }
    uint4* d = (uint4*)dst;
    const uint4* s = (const uint4*)ob;
#pragma unroll
    for (int j = 0; j < 6; ++j) d[j] = s[j];
}

// ---------------- self attention -------------------------------------------
__global__ void __launch_bounds__(128) attn_self()
{
    const int b = blockIdx.x, h = blockIdx.y, i = threadIdx.x;
    __shared__ float ks[NTOK * HD];
    __shared__ float vs[NTOK * HD];
    const float* base = g_qkv_self + (size_t)b * NTOK * 384;
    {
        const float4* kr = (const float4*)(base + i * 384 + 128 + h * HD);
        float4* kd = (float4*)(ks + i * HD);
        kd[0] = kr[0]; kd[1] = kr[1]; kd[2] = kr[2]; kd[3] = kr[3];
        const float4* vr = (const float4*)(base + i * 384 + 256 + h * HD);
        float4* vd = (float4*)(vs + i * HD);
        vd[0] = vr[0]; vd[1] = vr[1]; vd[2] = vr[2]; vd[3] = vr[3];
    }
    float q[HD];
    const float* qr = base + i * 384 + h * HD;
#pragma unroll
    for (int c = 0; c < HD; ++c) q[c] = qr[c] * 0.25f;
    __syncthreads();

    const float* mcol = g_maskT + (size_t)(b & 511) * 16384 + i;
    const float* bcol = g_biasT + h * 16384 + i;

    float mx = -1e30f, sm = 0.f, acc[HD] = {};
#pragma unroll 4
    for (int m = 0; m < NTOK; ++m) {
        const float4* kk = (const float4*)(ks + m * HD);
        float4 k0 = kk[0], k1 = kk[1], k2 = kk[2], k3 = kk[3];
        float s = mcol[m * 128] + bcol[m * 128];
        s += q[0]*k0.x + q[1]*k0.y + q[2]*k0.z + q[3]*k0.w;
        s += q[4]*k1.x + q[5]*k1.y + q[6]*k1.z + q[7]*k1.w;
        s += q[8]*k2.x + q[9]*k2.y + q[10]*k2.z + q[11]*k2.w;
        s += q[12]*k3.x + q[13]*k3.y + q[14]*k3.z + q[15]*k3.w;
        if (s > mx) {
            float corr = __expf(mx - s);
            sm *= corr;
#pragma unroll
            for (int c = 0; c < HD; ++c) acc[c] *= corr;
            mx = s;
        }
        float p = __expf(s - mx);
        sm += p;
        const float4* vv = (const float4*)(vs + m * HD);
        float4 v0 = vv[0], v1 = vv[1], v2 = vv[2], v3 = vv[3];
        acc[0] += p*v0.x; acc[1] += p*v0.y; acc[2]  += p*v0.z; acc[3]  += p*v0.w;
        acc[4] += p*v1.x; acc[5] += p*v1.y; acc[6]  += p*v1.z; acc[7]  += p*v1.w;
        acc[8] += p*v2.x; acc[9] += p*v2.y; acc[10] += p*v2.z; acc[11] += p*v2.w;
        acc[12]+= p*v3.x; acc[13]+= p*v3.y; acc[14] += p*v3.z; acc[15] += p*v3.w;
    }
    float inv = 1.f / sm;
    float o[HD];
#pragma unroll
    for (int c = 0; c < HD; ++c) o[c] = acc[c] * inv;
    store_triplets16(g_concat3 + ((size_t)b * NTOK + i) * 768 + (128 + h * HD) * 3, o);
}

// ---------------- mutual cross attention -----------------------------------
__global__ void __launch_bounds__(128) attn_mut()
{
    const int b = blockIdx.x, h = blockIdx.y, i = threadIdx.x;
    __shared__ float ks[NTOK * HD];
    __shared__ float vs[NTOK * HD];
    const float* base = g_qkv_mut + (size_t)b * NTOK * 384;
    {
        const float4* kr = (const float4*)(base + i * 384 + 128 + h * HD);
        float4* kd = (float4*)(ks + i * HD);
        kd[0] = kr[0]; kd[1] = kr[1]; kd[2] = kr[2]; kd[3] = kr[3];
        const float4* vr = (const float4*)(base + i * 384 + 256 + h * HD);
        float4* vd = (float4*)(vs + i * HD);
        vd[0] = vr[0]; vd[1] = vr[1]; vd[2] = vr[2]; vd[3] = vr[3];
    }
    const int qrow = (i < 64) ? (64 + i) : (i - 64);
    const int il   = (i < 64) ? i : (i - 64);
    const int kb   = (i < 64) ? 0 : 64;
    float q[HD];
    const float* qr = base + qrow * 384 + h * HD;
#pragma unroll
    for (int c = 0; c < HD; ++c) q[c] = qr[c] * 0.25f;
    __syncthreads();

    const float* mcol = g_maskT + (size_t)(b & 511) * 16384 + il;

    float mx = -1e30f, sm = 0.f, acc[HD] = {};
#pragma unroll 4
    for (int m = 0; m < 64; ++m) {
        const float4* kk = (const float4*)(ks + (kb + m) * HD);
        float4 k0 = kk[0], k1 = kk[1], k2 = kk[2], k3 = kk[3];
        float s = mcol[m * 128];
        s += q[0]*k0.x + q[1]*k0.y + q[2]*k0.z + q[3]*k0.w;
        s += q[4]*k1.x + q[5]*k1.y + q[6]*k1.z + q[7]*k1.w;
        s += q[8]*k2.x + q[9]*k2.y + q[10]*k2.z + q[11]*k2.w;
        s += q[12]*k3.x + q[13]*k3.y + q[14]*k3.z + q[15]*k3.w;
        if (s > mx) {
            float corr = __expf(mx - s);
            sm *= corr;
#pragma unroll
            for (int c = 0; c < HD; ++c) acc[c] *= corr;
            mx = s;
        }
        float p = __expf(s - mx);
        sm += p;
        const float4* vv = (const float4*)(vs + (kb + m) * HD);
        float4 v0 = vv[0], v1 = vv[1], v2 = vv[2], v3 = vv[3];
        acc[0] += p*v0.x; acc[1] += p*v0.y; acc[2]  += p*v0.z; acc[3]  += p*v0.w;
        acc[4] += p*v1.x; acc[5] += p*v1.y; acc[6]  += p*v1.z; acc[7]  += p*v1.w;
        acc[8] += p*v2.x; acc[9] += p*v2.y; acc[10] += p*v2.z; acc[11] += p*v2.w;
        acc[12]+= p*v3.x; acc[13]+= p*v3.y; acc[14] += p*v3.z; acc[15] += p*v3.w;
    }
    float inv = 1.f / sm;
    float o[HD];
#pragma unroll
    for (int c = 0; c < HD; ++c) o[c] = acc[c] * inv;
    store_triplets16(g_concat3 + ((size_t)b * NTOK + i) * 768 + (h * HD) * 3, o);
}

// ---------------- launch ----------------------------------------------------
extern "C" void kernel_launch(void* const* d_in, const int* in_sizes, int n_in,
                              void* d_out, int out_size)
{
    const float* x         = (const float*)d_in[0];
    const float* mask      = (const float*)d_in[1];
    const float* w_self    = (const float*)d_in[2];
    const float* w_mut     = (const float*)d_in[3];
    const float* w_proj    = (const float*)d_in[4];
    const float* b_proj    = (const float*)d_in[5];
    const float* rpe_table = (const float*)d_in[6];
    const float* pe        = (const float*)d_in[7];
    const int*   rpe_index = (const int*)d_in[8];
    float* out = (float*)d_out;

    unsigned short *xs, *xpes, *cc;
    unsigned short *ws, *wm, *wp;
    float *qs, *qm;
    cudaGetSymbolAddress((void**)&ws, g_ws3);
    cudaGetSymbolAddress((void**)&wm, g_wm3);
    cudaGetSymbolAddress((void**)&wp, g_wp3);
    cudaGetSymbolAddress((void**)&xs, g_xs3);
    cudaGetSymbolAddress((void**)&xpes, g_xpes3);
    cudaGetSymbolAddress((void**)&qs, g_qkv_self);
    cudaGetSymbolAddress((void**)&qm, g_qkv_mut);
    cudaGetSymbolAddress((void**)&cc, g_concat3);

    const int SMEM = 4 * STAGE_ELEMS * (int)sizeof(__nv_bfloat16);   // 73728 B
    cudaFuncSetAttribute(gemm_bf16<384, 384, false>,
                         cudaFuncAttributeMaxDynamicSharedMemorySize, SMEM);
    cudaFuncSetAttribute(gemm_bf16<768, 128, true>,
                         cudaFuncAttributeMaxDynamicSharedMemorySize, SMEM);

    // prep (4 launches so the ncu -s 5 capture lands on the 6th = QKV-mut GEMM)
    wsplit_all<<<512, 256>>>(w_self, w_mut, w_proj);
    xprep<<<MROWS * 128 / 8 / 256, 256>>>(x, pe);
    biasT_prep<<<64, 256>>>(rpe_index, rpe_table);
    maskT_prep<<<dim3(4, 4, 512), dim3(32, 8)>>>(mask);

    // QKV GEMMs (K' = 384); grid.x = col blocks (fast) for L2 reuse of A
    gemm_bf16<384, 384, false><<<dim3(3, 1024), 256, SMEM>>>(
        (const __nv_bfloat16*)xs,   (const __nv_bfloat16*)ws, nullptr, qs);
    gemm_bf16<384, 384, false><<<dim3(3, 1024), 256, SMEM>>>(
        (const __nv_bfloat16*)xpes, (const __nv_bfloat16*)wm, nullptr, qm);

    // attention
    attn_self<<<dim3(WB, NHEADS), 128>>>();
    attn_mut <<<dim3(WB, NHEADS), 128>>>();

    // projection (K' = 768)
    gemm_bf16<768, 128, true><<<dim3(1, 1024), 256, SMEM>>>(
        (const __nv_bfloat16*)cc, (const __nv_bfloat16*)wp, b_proj, out);
}